// round 1
// baseline (speedup 1.0000x reference)
#include <cuda_runtime.h>
#include <cuda_fp16.h>
#include <math.h>

#define B_DIM 512
#define IN_DIM 4096
#define OUT_DIM 11008

// Scratch (allocation-free rule: __device__ globals)
__device__ __half g_W16[(size_t)OUT_DIM * IN_DIM];   // ~90 MB fp16 weights
__device__ __half g_x16[(size_t)B_DIM * IN_DIM];     // ~4 MB fp16 activations

// ---------------------------------------------------------------------------
// Kernel 1: dequantize QINS weights -> fp16, via 256-entry LUT (no exp in hot loop)
// ---------------------------------------------------------------------------
__global__ __launch_bounds__(256) void dequant_kernel(
    const int* __restrict__ stored, const int* __restrict__ sign,
    const float* __restrict__ log_min_p, const float* __restrict__ log_max_p)
{
    __shared__ unsigned short lut[256];
    int t = threadIdx.x;
    if (t < 256) {
        float lmin = *log_min_p;
        float lmax = *log_max_p;
        float nrm = (255.0f - (float)t) * (1.0f / 254.0f);
        lut[t] = __half_as_ushort(__float2half(expf(lmin + nrm * (lmax - lmin))));
    }
    __syncthreads();

    size_t base = ((size_t)blockIdx.x * blockDim.x + threadIdx.x) * 8;
    const int4* st4 = reinterpret_cast<const int4*>(stored + base);
    const int4* sg4 = reinterpret_cast<const int4*>(sign + base);
    int4 s0 = st4[0];
    int4 s1 = st4[1];
    int4 g0 = sg4[0];
    int4 g1 = sg4[1];

    unsigned h[8];
    {
        const int sv[8] = {s0.x, s0.y, s0.z, s0.w, s1.x, s1.y, s1.z, s1.w};
        const int gv[8] = {g0.x, g0.y, g0.z, g0.w, g1.x, g1.y, g1.z, g1.w};
#pragma unroll
        for (int i = 0; i < 8; i++) {
            unsigned hb = (unsigned)lut[sv[i] & 0xFF];
            // sign is +1 / -1 : -1 has bit 31 set -> flip fp16 sign bit
            hb ^= ((((unsigned)gv[i]) >> 16) & 0x8000u);
            h[i] = hb;
        }
    }
    uint4 outv;
    outv.x = h[0] | (h[1] << 16);
    outv.y = h[2] | (h[3] << 16);
    outv.z = h[4] | (h[5] << 16);
    outv.w = h[6] | (h[7] << 16);
    *reinterpret_cast<uint4*>(&g_W16[base]) = outv;
}

// ---------------------------------------------------------------------------
// Kernel 2: x fp32 -> fp16
// ---------------------------------------------------------------------------
__global__ __launch_bounds__(256) void xconv_kernel(const float* __restrict__ x)
{
    size_t i = ((size_t)blockIdx.x * blockDim.x + threadIdx.x) * 4;
    float4 v = *reinterpret_cast<const float4*>(x + i);
    __half2 a = __floats2half2_rn(v.x, v.y);
    __half2 b = __floats2half2_rn(v.z, v.w);
    uint2 o;
    o.x = *reinterpret_cast<unsigned*>(&a);
    o.y = *reinterpret_cast<unsigned*>(&b);
    *reinterpret_cast<uint2*>(&g_x16[i]) = o;
}

// ---------------------------------------------------------------------------
// Kernel 3: GEMM  out[b][o] = (sum_k x16[b][k]*W16[o][k] + bias[o]) * scale[o]
//   Tiles: BM=128, BN=128, BK=32, 256 threads (8 warps = 2x4), warp tile 64x32
//   mma.sync.m16n8k16 fp16 -> fp32 accumulate. cp.async double-buffered smem.
// ---------------------------------------------------------------------------
#define BM 128
#define BN 128
#define BK 32
#define SKEW 8
#define BSTRIDE (BK + SKEW)   // 40 halves per row => 80B, conflict-free ldmatrix phases

__device__ __forceinline__ void cp_async16(void* smem, const void* gmem) {
    unsigned saddr = (unsigned)__cvta_generic_to_shared(smem);
    asm volatile("cp.async.cg.shared.global [%0], [%1], 16;\n" :: "r"(saddr), "l"(gmem));
}
__device__ __forceinline__ void cp_commit() {
    asm volatile("cp.async.commit_group;\n" ::: "memory");
}
template <int N>
__device__ __forceinline__ void cp_wait() {
    asm volatile("cp.async.wait_group %0;\n" :: "n"(N) : "memory");
}
__device__ __forceinline__ void ldm_x4(unsigned& r0, unsigned& r1, unsigned& r2, unsigned& r3,
                                       const __half* p) {
    unsigned a = (unsigned)__cvta_generic_to_shared(p);
    asm volatile("ldmatrix.sync.aligned.m8n8.x4.shared.b16 {%0,%1,%2,%3}, [%4];\n"
                 : "=r"(r0), "=r"(r1), "=r"(r2), "=r"(r3) : "r"(a));
}
__device__ __forceinline__ void mma16816(float* d, const unsigned* a, const unsigned* b) {
    asm volatile(
        "mma.sync.aligned.m16n8k16.row.col.f32.f16.f16.f32 "
        "{%0,%1,%2,%3}, {%4,%5,%6,%7}, {%8,%9}, {%0,%1,%2,%3};\n"
        : "+f"(d[0]), "+f"(d[1]), "+f"(d[2]), "+f"(d[3])
        : "r"(a[0]), "r"(a[1]), "r"(a[2]), "r"(a[3]), "r"(b[0]), "r"(b[1]));
}

__global__ __launch_bounds__(256) void gemm_kernel(
    const float* __restrict__ bias, const float* __restrict__ scale,
    float* __restrict__ out)
{
    __shared__ __half sA[2][BM * BSTRIDE];
    __shared__ __half sB[2][BN * BSTRIDE];

    const int bm = blockIdx.y;
    const int bn = blockIdx.x;
    const int tid = threadIdx.x;
    const int warp = tid >> 5;
    const int lane = tid & 31;
    const int wm = warp >> 2;  // 0..1 (M direction, 64 rows each)
    const int wn = warp & 3;   // 0..3 (N direction, 32 cols each)

    const __half* gA = g_x16 + (size_t)bm * BM * IN_DIM;
    const __half* gB = g_W16 + (size_t)bn * BN * IN_DIM;

    float acc[4][4][4];
#pragma unroll
    for (int mi = 0; mi < 4; mi++)
#pragma unroll
        for (int ni = 0; ni < 4; ni++)
#pragma unroll
            for (int r = 0; r < 4; r++) acc[mi][ni][r] = 0.0f;

    // tile loader: 128 rows x 32 cols fp16, 16B chunks; 512 chunks / 256 thr = 2 each
    auto load_tile = [&](int stage, int k0) {
#pragma unroll
        for (int i = 0; i < 2; i++) {
            int id = tid + i * 256;
            int row = id >> 2;
            int cc = id & 3;
            cp_async16(&sA[stage][row * BSTRIDE + cc * 8],
                       gA + (size_t)row * IN_DIM + k0 + cc * 8);
        }
#pragma unroll
        for (int i = 0; i < 2; i++) {
            int id = tid + i * 256;
            int row = id >> 2;
            int cc = id & 3;
            cp_async16(&sB[stage][row * BSTRIDE + cc * 8],
                       gB + (size_t)row * IN_DIM + k0 + cc * 8);
        }
    };

    load_tile(0, 0);
    cp_commit();
    load_tile(1, BK);
    cp_commit();

    const int nk = IN_DIM / BK;  // 128
    for (int kt = 0; kt < nk; ++kt) {
        cp_wait<1>();
        __syncthreads();
        const int s = kt & 1;

#pragma unroll
        for (int ks = 0; ks < 2; ks++) {
            // A fragments: 4 m16 tiles
            unsigned afr[4][4];
#pragma unroll
            for (int mi = 0; mi < 4; mi++) {
                const __half* p = &sA[s][(wm * 64 + mi * 16 + (lane & 15)) * BSTRIDE +
                                         ks * 16 + (lane >> 4) * 8];
                ldm_x4(afr[mi][0], afr[mi][1], afr[mi][2], afr[mi][3], p);
            }
            // B fragments: 4 n8 tiles, loaded as 2 x ldmatrix.x4 (16 n-rows each)
            unsigned bfr[4][2];
#pragma unroll
            for (int nj = 0; nj < 2; nj++) {
                const __half* p = &sB[s][(wn * 32 + nj * 16 + ((lane >> 4) & 1) * 8 +
                                          (lane & 7)) * BSTRIDE +
                                         ks * 16 + ((lane >> 3) & 1) * 8];
                unsigned r0, r1, r2, r3;
                ldm_x4(r0, r1, r2, r3, p);
                bfr[2 * nj + 0][0] = r0;
                bfr[2 * nj + 0][1] = r1;
                bfr[2 * nj + 1][0] = r2;
                bfr[2 * nj + 1][1] = r3;
            }
#pragma unroll
            for (int mi = 0; mi < 4; mi++)
#pragma unroll
                for (int ni = 0; ni < 4; ni++)
                    mma16816(acc[mi][ni], afr[mi], bfr[ni]);
        }

        __syncthreads();
        if (kt + 2 < nk) load_tile(s, (kt + 2) * BK);
        cp_commit();
    }

    // Epilogue: (acc + bias) * scale, fp32 out, row-major [B_DIM][OUT_DIM]
    const int row0 = bm * BM + wm * 64;
    const int col0 = bn * BN + wn * 32;
    const int cl = (lane & 3) * 2;
    const int rl = lane >> 2;

    float bs[4][2], sc[4][2];
#pragma unroll
    for (int ni = 0; ni < 4; ni++) {
        int c = col0 + ni * 8 + cl;
        bs[ni][0] = bias[c];
        bs[ni][1] = bias[c + 1];
        sc[ni][0] = scale[c];
        sc[ni][1] = scale[c + 1];
    }

#pragma unroll
    for (int mi = 0; mi < 4; mi++) {
#pragma unroll
        for (int ni = 0; ni < 4; ni++) {
            int r = row0 + mi * 16 + rl;
            int c = col0 + ni * 8 + cl;
            float2 v0, v1;
            v0.x = (acc[mi][ni][0] + bs[ni][0]) * sc[ni][0];
            v0.y = (acc[mi][ni][1] + bs[ni][1]) * sc[ni][1];
            v1.x = (acc[mi][ni][2] + bs[ni][0]) * sc[ni][0];
            v1.y = (acc[mi][ni][3] + bs[ni][1]) * sc[ni][1];
            *reinterpret_cast<float2*>(&out[(size_t)r * OUT_DIM + c]) = v0;
            *reinterpret_cast<float2*>(&out[(size_t)(r + 8) * OUT_DIM + c]) = v1;
        }
    }
}

// ---------------------------------------------------------------------------
// Launch
// ---------------------------------------------------------------------------
extern "C" void kernel_launch(void* const* d_in, const int* in_sizes, int n_in,
                              void* d_out, int out_size)
{
    const float* x       = (const float*)d_in[0];
    const int*   stored  = (const int*)d_in[1];
    const int*   sign    = (const int*)d_in[2];
    const float* log_min = (const float*)d_in[3];
    const float* log_max = (const float*)d_in[4];
    const float* scale   = (const float*)d_in[5];
    const float* bias    = (const float*)d_in[6];
    float* out = (float*)d_out;

    // 1) dequant W:  45088768 elems / (256 thr * 8 elem) = 22016 blocks
    dequant_kernel<<<22016, 256>>>(stored, sign, log_min, log_max);
    // 2) convert x:  2097152 / (256*4) = 2048 blocks
    xconv_kernel<<<2048, 256>>>(x);
    // 3) GEMM: grid (N tiles = 86, M tiles = 4)
    dim3 grid(OUT_DIM / BN, B_DIM / BM);
    gemm_kernel<<<grid, 256>>>(bias, scale, out);
}